// round 8
// baseline (speedup 1.0000x reference)
#include <cuda_runtime.h>
#include <cuda_bf16.h>

#define NPTS    500000
#define C_OUT   64
#define GRID_H  256
#define GRID_W  256
#define NCELL   (GRID_H * GRID_W)
#define BLK     256
#define NTH     256
#define NBLK    ((NPTS + BLK - 1) / BLK)
#define KC      26              // 8 chunks * 26 = 208
#define HP      260             // padded point-stride for H

// shared float offsets
#define OW1  0            // 208*64 = 13312
#define OW2  13312        // 64*64  = 4096
#define OXD  17408        // 26*512 = 13312 (X duplicated pairs)
#define OH   30720        // 64*260 = 16640
#define OB1  47360
#define OG   47424
#define OB   47488
#define OB2  47552
#define OMP  47616        // 64 float2 (freq, phase)
#define OFL  47744        // 256 ints
#define SMF  48000
#define SMB  (SMF * 4)    // 192000 B -> 1 CTA/SM

__device__ float g_accum[NCELL * C_OUT];   // cell-major scratch [cell][ch]
__device__ float g_counts[NCELL];

__device__ __forceinline__ void fma2(unsigned long long& d, unsigned long long a,
                                     unsigned long long b) {
    asm("fma.rn.f32x2 %0, %1, %2, %0;" : "+l"(d) : "l"(a), "l"(b));
}
__device__ __forceinline__ unsigned long long dup2(float v) {
    unsigned long long r; asm("mov.b64 %0, {%1, %1};" : "=l"(r) : "f"(v)); return r;
}
__device__ __forceinline__ float2 up2(unsigned long long a) {
    float2 r; asm("mov.b64 {%0, %1}, %2;" : "=f"(r.x), "=f"(r.y) : "l"(a)); return r;
}
__device__ __forceinline__ void red4(float* p, float a, float b, float c, float d) {
    asm volatile("red.global.add.v4.f32 [%0], {%1, %2, %3, %4};"
                 :: "l"(p), "f"(a), "f"(b), "f"(c), "f"(d) : "memory");
}

__global__ __launch_bounds__(NTH, 1)
void p2g_kernel(const float* __restrict__ pos,
                const float* __restrict__ feat,
                const float* __restrict__ W1,
                const float* __restrict__ b1,
                const float* __restrict__ lng,
                const float* __restrict__ lnb,
                const float* __restrict__ W2,
                const float* __restrict__ b2,
                const int*   __restrict__ ax1p,
                const int*   __restrict__ ax2p) {
    extern __shared__ float sm[];
    int* sFlat = (int*)&sm[OFL];
    const int tid  = threadIdx.x;
    const int base = blockIdx.x * BLK;

    // ---- stage weights + tables ----
    {
        const float4* w1v = (const float4*)W1;
        float4* d1 = (float4*)&sm[OW1];
#pragma unroll
        for (int i = 0; i < 13; ++i) d1[tid + i * 256] = w1v[tid + i * 256];
        const float4* w2v = (const float4*)W2;
        float4* d2 = (float4*)&sm[OW2];
#pragma unroll
        for (int i = 0; i < 4; ++i) d2[tid + i * 256] = w2v[tid + i * 256];
        if (tid < 64) {
            int f = tid & 31, t = tid >> 5;
            sm[OMP + 2 * tid]     = exp2f((float)f * 0.03125f) * 1.57079632679489662f;
            sm[OMP + 2 * tid + 1] = t ? 1.57079632679489662f : 0.0f;
            sm[OB1 + tid] = b1[tid];
            sm[OG  + tid] = lng[tid];
            sm[OB  + tid] = lnb[tid];
            sm[OB2 + tid] = b2[tid];
        }
    }

    // ---- per-thread point (thread tid owns point tid of this CTA) ----
    const int pg = min(base + tid, NPTS - 1);
    float pd0 = pos[pg * 3 + 0];
    float pd1 = pos[pg * 3 + 1];
    float pd2 = pos[pg * 3 + 2];
    float fr[16];
    {
        const float4* fv = (const float4*)(feat + pg * 16);
#pragma unroll
        for (int i = 0; i < 4; ++i) {
            float4 t = fv[i];
            fr[4 * i + 0] = t.x; fr[4 * i + 1] = t.y;
            fr[4 * i + 2] = t.z; fr[4 * i + 3] = t.w;
        }
    }
    {
        int a1 = *ax1p, a2 = *ax2p;
        float v1 = (a1 == 0) ? pd0 : ((a1 == 1) ? pd1 : pd2);
        float v2 = (a2 == 0) ? pd0 : ((a2 == 1) ? pd1 : pd2);
        float n1 = fminf(fmaxf((v1 + 1.0f) * 0.5f, 0.0f), 1.0f);
        float n2 = fminf(fmaxf((v2 + 1.0f) * 0.5f, 0.0f), 1.0f);
        int i1 = min(max((int)floorf(n1 * (float)GRID_H), 0), GRID_H - 1);
        int i2 = min(max((int)floorf(n2 * (float)GRID_W), 0), GRID_W - 1);
        sFlat[tid] = i1 * GRID_W + i2;
    }

    const int ptg = tid >> 2;     // 0..63 : points ptg*4 .. +3
    const int chg = tid & 3;      // 0..3  : channels chg*16 .. +15

    unsigned long long acc[4][8];   // [pt][chpair], 64 floats
#pragma unroll
    for (int a = 0; a < 4; ++a)
#pragma unroll
        for (int b = 0; b < 8; ++b) acc[a][b] = 0ull;

    __syncthreads();

    // ================= GEMM1: 8 chunks of K=26 =================
#pragma unroll 1
    for (int c = 0; c < 8; ++c) {
        const int k0 = c * KC;
        // build own point's X column, duplicated pairs
#pragma unroll 1
        for (int i = 0; i < KC; ++i) {
            int k = k0 + i;
            float v;
            if (k < 16) {
                v = fr[k];
            } else {
                int j = k - 16;
                float pdx = (j < 64) ? pd0 : ((j < 128) ? pd1 : pd2);
                float2 mp = *(const float2*)&sm[OMP + 2 * (j & 63)];
                v = __sinf(fmaf(pdx, mp.x, mp.y));
            }
            *(float2*)&sm[OXD + i * 512 + 2 * tid] = make_float2(v, v);
        }
        __syncthreads();

#pragma unroll
        for (int i = 0; i < KC; ++i) {
            const float* xr = &sm[OXD + i * 512 + ptg * 8];
            ulonglong2 xa = *(const ulonglong2*)xr;        // dup(p0), dup(p1)
            ulonglong2 xb = *(const ulonglong2*)(xr + 4);  // dup(p2), dup(p3)
            unsigned long long xp[4] = {xa.x, xa.y, xb.x, xb.y};
            const float* wr = &sm[OW1 + (k0 + i) * 64 + chg * 16];
            ulonglong2 w0 = *(const ulonglong2*)wr;
            ulonglong2 w1 = *(const ulonglong2*)(wr + 4);
            ulonglong2 w2 = *(const ulonglong2*)(wr + 8);
            ulonglong2 w3 = *(const ulonglong2*)(wr + 12);
            unsigned long long wp[8] = {w0.x, w0.y, w1.x, w1.y,
                                        w2.x, w2.y, w3.x, w3.y};
#pragma unroll
            for (int a = 0; a < 4; ++a)
#pragma unroll
                for (int b = 0; b < 8; ++b) fma2(acc[a][b], xp[a], wp[b]);
        }
        __syncthreads();
    }

    // ---- bias + LayerNorm + exact GELU (4 threads per point, shfl 1,2) ----
    {
        float h[4][16];
#pragma unroll
        for (int a = 0; a < 4; ++a)
#pragma unroll
            for (int cp = 0; cp < 8; ++cp) {
                float2 t = up2(acc[a][cp]);
                h[a][2 * cp]     = t.x + sm[OB1 + chg * 16 + 2 * cp];
                h[a][2 * cp + 1] = t.y + sm[OB1 + chg * 16 + 2 * cp + 1];
            }
        float s[4], s2[4];
#pragma unroll
        for (int a = 0; a < 4; ++a) {
            s[a] = 0.0f; s2[a] = 0.0f;
#pragma unroll
            for (int j = 0; j < 16; ++j) { s[a] += h[a][j]; s2[a] += h[a][j] * h[a][j]; }
        }
#pragma unroll
        for (int o = 1; o < 4; o <<= 1) {
#pragma unroll
            for (int a = 0; a < 4; ++a) {
                s[a]  += __shfl_xor_sync(0xFFFFFFFF, s[a],  o);
                s2[a] += __shfl_xor_sync(0xFFFFFFFF, s2[a], o);
            }
        }
#pragma unroll
        for (int a = 0; a < 4; ++a) {
            float mu   = s[a] * (1.0f / 64.0f);
            float var  = s2[a] * (1.0f / 64.0f) - mu * mu;
            float rstd = rsqrtf(var + 1e-5f);
#pragma unroll
            for (int j = 0; j < 16; ++j) {
                float v = (h[a][j] - mu) * rstd * sm[OG + chg * 16 + j]
                          + sm[OB + chg * 16 + j];
                h[a][j] = 0.5f * v * (1.0f + erff(v * 0.70710678118654752f));
            }
        }
        // store H [ch][pt] stride HP
#pragma unroll
        for (int j = 0; j < 16; ++j) {
            int ch = chg * 16 + j;
            float4 o = {h[0][j], h[1][j], h[2][j], h[3][j]};
            *(float4*)&sm[OH + ch * HP + ptg * 4] = o;
        }
    }
    __syncthreads();

    // ================= GEMM2 (same tiling; x dup via MOV) =================
    unsigned long long a2[4][8];
#pragma unroll
    for (int a = 0; a < 4; ++a)
#pragma unroll
        for (int b = 0; b < 8; ++b) a2[a][b] = 0ull;

#pragma unroll 8
    for (int k = 0; k < 64; ++k) {
        float4 xq = *(const float4*)&sm[OH + k * HP + ptg * 4];
        unsigned long long xp[4] = {dup2(xq.x), dup2(xq.y), dup2(xq.z), dup2(xq.w)};
        const float* wr = &sm[OW2 + k * 64 + chg * 16];
        ulonglong2 w0 = *(const ulonglong2*)wr;
        ulonglong2 w1 = *(const ulonglong2*)(wr + 4);
        ulonglong2 w2 = *(const ulonglong2*)(wr + 8);
        ulonglong2 w3 = *(const ulonglong2*)(wr + 12);
        unsigned long long wp[8] = {w0.x, w0.y, w1.x, w1.y,
                                    w2.x, w2.y, w3.x, w3.y};
#pragma unroll
        for (int a = 0; a < 4; ++a)
#pragma unroll
            for (int b = 0; b < 8; ++b) fma2(a2[a][b], xp[a], wp[b]);
    }

    // ---- scatter: red.v4 into cell-major scratch ----
    float bias[16];
#pragma unroll
    for (int j = 0; j < 16; ++j) bias[j] = sm[OB2 + chg * 16 + j];

#pragma unroll
    for (int pl = 0; pl < 4; ++pl) {
        int pG = base + ptg * 4 + pl;
        if (pG < NPTS) {
            int fl = sFlat[ptg * 4 + pl];
            float* dst = &g_accum[fl * 64 + chg * 16];
#pragma unroll
            for (int q = 0; q < 4; ++q) {
                float2 t0 = up2(a2[pl][2 * q]);
                float2 t1 = up2(a2[pl][2 * q + 1]);
                red4(dst + 4 * q,
                     t0.x + bias[4 * q + 0], t0.y + bias[4 * q + 1],
                     t1.x + bias[4 * q + 2], t1.y + bias[4 * q + 3]);
            }
            if (chg == 0) atomicAdd(&g_counts[fl], 1.0f);
        }
    }
}

// transpose [cell][ch] -> [ch][cell], mean-divide, re-zero scratch
__global__ __launch_bounds__(256)
void finalize_kernel(float* __restrict__ out) {
    __shared__ float tile[64][65];
    __shared__ float cnt[64];
    const int tid = threadIdx.x;
    const int cell0 = blockIdx.x * 64;

#pragma unroll
    for (int it = 0; it < 4; ++it) {
        int lin = it * 256 + tid;
        float4* src = (float4*)&g_accum[cell0 * 64] + lin;
        float4 v = *src;
        int row = lin >> 4, col4 = (lin & 15) * 4;
        tile[row][col4 + 0] = v.x;
        tile[row][col4 + 1] = v.y;
        tile[row][col4 + 2] = v.z;
        tile[row][col4 + 3] = v.w;
        *src = make_float4(0.0f, 0.0f, 0.0f, 0.0f);
    }
    if (tid < 64) {
        cnt[tid] = 1.0f / fmaxf(g_counts[cell0 + tid], 1.0f);
        g_counts[cell0 + tid] = 0.0f;
    }
    __syncthreads();

#pragma unroll
    for (int it = 0; it < 4; ++it) {
        int lin = it * 256 + tid;
        int ch = lin >> 4, cl4 = (lin & 15) * 4;
        float4 o;
        o.x = tile[cl4 + 0][ch] * cnt[cl4 + 0];
        o.y = tile[cl4 + 1][ch] * cnt[cl4 + 1];
        o.z = tile[cl4 + 2][ch] * cnt[cl4 + 2];
        o.w = tile[cl4 + 3][ch] * cnt[cl4 + 3];
        *(float4*)&out[ch * NCELL + cell0 + cl4] = o;
    }
}

extern "C" void kernel_launch(void* const* d_in, const int* in_sizes, int n_in,
                              void* d_out, int out_size) {
    const float* pos  = (const float*)d_in[0];
    const float* feat = (const float*)d_in[1];
    const float* W1   = (const float*)d_in[2];
    const float* b1   = (const float*)d_in[3];
    const float* lng  = (const float*)d_in[4];
    const float* lnb  = (const float*)d_in[5];
    const float* W2   = (const float*)d_in[6];
    const float* b2   = (const float*)d_in[7];
    const int*   ax1  = (const int*)d_in[8];
    const int*   ax2  = (const int*)d_in[9];
    float* out = (float*)d_out;

    cudaFuncSetAttribute(p2g_kernel, cudaFuncAttributeMaxDynamicSharedMemorySize, SMB);

    // g_accum / g_counts start zeroed (device globals); finalize_kernel
    // re-zeroes them each call, so no separate zero pass is needed.
    p2g_kernel<<<NBLK, NTH, SMB>>>(pos, feat, W1, b1, lng, lnb, W2, b2, ax1, ax2);
    finalize_kernel<<<NCELL / 64, 256>>>(out);
}